// round 14
// baseline (speedup 1.0000x reference)
#include <cuda_runtime.h>
#include <cuda_fp16.h>

// Problem constants
#define NN 50000
#define DD 128
#define EE 800000
#define ET (EE + NN)     // edges + self loops
#define F1 256
#define F2 32
#define NB ((NN + 255) / 256)   // 196 scan blocks

// ---------------- scratch (device globals; no allocations) ----------------
__device__ __half g_W1h[F1 * DD];    // W1^T [n=256][k=128] fp16
__device__ __half g_W2h[F2 * F1];    // W2^T [n=32][k=256] fp16
__device__ __half g_fcWh[DD * F2];   // fcW^T [n=128][k=32] fp16
__device__ __half g_xl1h[NN * F1];   // fp16 xl1 for aggregation gather
__device__ __half g_h1h[NN * F1];    // relu(agg1 + b1), fp16 for gemm2
__device__ float  g_ls1[NN * 4];
__device__ float  g_ld1[NN * 4];

__device__ __half g_xl2h[NN * F2];   // fp16 xl2 for agg2 gather
__device__ float  g_ls2[NN];
__device__ float  g_ld2[NN];

// CSR structures (g_cnt self-restores to 0; g_total reset in k_hist)
__device__ int  g_cnt[NN];
__device__ int2 g_offdeg[NN];        // (offset, degree) per dst
__device__ int  g_cur[NN];
__device__ int  g_total;
__device__ int  g_src[ET];           // src node per grouped edge

// ---------------- side stream for DAG capture (created once at load) -------
struct SideStream {
    cudaStream_t s = nullptr;
    cudaEvent_t fork = nullptr, join = nullptr;
    bool ok = false;
    SideStream() {
        if (cudaStreamCreateWithFlags(&s, cudaStreamNonBlocking) == cudaSuccess &&
            cudaEventCreateWithFlags(&fork, cudaEventDisableTiming) == cudaSuccess &&
            cudaEventCreateWithFlags(&join, cudaEventDisableTiming) == cudaSuccess)
            ok = true;
    }
};
static SideStream g_ss;

// ---------------- helpers ----------------
__device__ __forceinline__ float lrelu(float e) { return fmaxf(e, 0.2f * e); }

__device__ __forceinline__ void mma_f16(float& c0, float& c1, float& c2, float& c3,
                                        unsigned a0, unsigned a1, unsigned a2, unsigned a3,
                                        unsigned b0, unsigned b1) {
    asm volatile("mma.sync.aligned.m16n8k16.row.col.f32.f16.f16.f32 "
                 "{%0,%1,%2,%3}, {%4,%5,%6,%7}, {%8,%9}, {%0,%1,%2,%3};"
                 : "+f"(c0), "+f"(c1), "+f"(c2), "+f"(c3)
                 : "r"(a0), "r"(a1), "r"(a2), "r"(a3), "r"(b0), "r"(b1));
}
__device__ __forceinline__ void ldsm_x4(unsigned& r0, unsigned& r1, unsigned& r2, unsigned& r3,
                                        unsigned addr) {
    asm volatile("ldmatrix.sync.aligned.m8n8.x4.shared.b16 {%0,%1,%2,%3}, [%4];"
                 : "=r"(r0), "=r"(r1), "=r"(r2), "=r"(r3) : "r"(addr));
}

// ------------- weight prep: W1/W2/fcW -> fp16 transposed --------------------
__global__ void k_prep(const float* __restrict__ W1, const float* __restrict__ W2,
                       const float* __restrict__ fcW) {
    int i = blockIdx.x * 256 + threadIdx.x;   // 32768 threads
    {   // W1 [128][256] -> [n][k]
        int k = i >> 8, n = i & 255;
        g_W1h[n * 128 + k] = __float2half_rn(W1[i]);
    }
    if (i < 8192) {   // W2 [256][32] -> [n][k]
        int k = i >> 5, n = i & 31;
        g_W2h[n * 256 + k] = __float2half_rn(W2[i]);
    }
    if (i < 4096) {   // fcW [32][128] -> [n][k]
        int k = i >> 7, n = i & 127;
        g_fcWh[n * 32 + k] = __float2half_rn(fcW[i]);
    }
}

// ---------------- CSR build ----------------
__global__ void k_hist(const int* __restrict__ ei) {
    int i = blockIdx.x * blockDim.x + threadIdx.x;
    if (i == 0) g_total = 0;              // reset scan base counter
    if (i * 4 >= EE) return;
    int4 d4 = *(const int4*)(ei + EE + i * 4);
    atomicAdd(&g_cnt[d4.x], 1);
    atomicAdd(&g_cnt[d4.y], 1);
    atomicAdd(&g_cnt[d4.z], 1);
    atomicAdd(&g_cnt[d4.w], 1);
}

__global__ void k_scan() {
    __shared__ int wsum[8];
    __shared__ int sbase;
    int tid = threadIdx.x;
    int t = blockIdx.x * 256 + tid;
    int v = 0;
    if (t < NN) { v = g_cnt[t] + 1; g_cnt[t] = 0; }   // +1 = self loop; restore 0
    int lane = tid & 31, wid = tid >> 5;
    int incl = v;
#pragma unroll
    for (int o = 1; o < 32; o <<= 1) {
        int n = __shfl_up_sync(0xffffffffu, incl, o);
        if (lane >= o) incl += n;
    }
    if (lane == 31) wsum[wid] = incl;
    __syncthreads();
    if (wid == 0) {
        int s = (lane < 8) ? wsum[lane] : 0;
#pragma unroll
        for (int o = 1; o < 8; o <<= 1) {
            int n = __shfl_up_sync(0xffffffffu, s, o);
            if (lane >= o) s += n;
        }
        if (lane < 8) wsum[lane] = s;
        if (lane == 7) sbase = atomicAdd(&g_total, s);  // s = block total
    }
    __syncthreads();
    int base = (wid > 0) ? wsum[wid - 1] : 0;
    if (t < NN) {
        int off = sbase + base + incl - v;
        g_offdeg[t] = make_int2(off, v);
        g_cur[t] = off;
    }
}

__global__ void k_scatter(const int* __restrict__ ei) {
    int i = (blockIdx.x * blockDim.x + threadIdx.x) * 4;
    if (i >= ET) return;
    if (i < EE) {   // EE divisible by 4
        int4 s4 = *(const int4*)(ei + i);
        int4 d4 = *(const int4*)(ei + EE + i);
        int p0 = atomicAdd(&g_cur[d4.x], 1);
        int p1 = atomicAdd(&g_cur[d4.y], 1);
        int p2 = atomicAdd(&g_cur[d4.z], 1);
        int p3 = atomicAdd(&g_cur[d4.w], 1);
        g_src[p0] = s4.x;
        g_src[p1] = s4.y;
        g_src[p2] = s4.z;
        g_src[p3] = s4.w;
    } else {
#pragma unroll
        for (int u = 0; u < 4; u++) {
            int n = i + u - EE;
            int pos = atomicAdd(&g_cur[n], 1);
            g_src[pos] = n;
        }
    }
}

// ---------------- GEMM1 (fp16 mma + ldmatrix) + fused logits1 ---------------
// Cs aliased onto Bs region (Bs dead after mainloop; refilled next head).
__global__ __launch_bounds__(128) void k_gemm1(const float* __restrict__ x,
                                               const float* __restrict__ as1,
                                               const float* __restrict__ ad1) {
    __shared__ __half As[64 * 136];   // [m][k=128], pad 136
    __shared__ __half Bs[64 * 136];   // [n][k=128]; reused as Cs[64][72]
    __shared__ float  sA[64], sD[64];
    __half* Cs = Bs;

    int tid = threadIdx.x;
    int lane = tid & 31, w = tid >> 5;
    int n0 = blockIdx.x * 64;
    int m0 = w * 16;
    int r4 = lane >> 2, c4 = lane & 3;
    int g8 = lane >> 3, r8 = lane & 7;

    // load x tile -> As fp16 ONCE
#pragma unroll
    for (int i = 0; i < 16; i++) {
        int q = tid + i * 128;
        int row = q >> 5, cq = (q & 31) * 4;
        int gn = n0 + row;
        float4 v = make_float4(0,0,0,0);
        if (gn < NN) v = *(const float4*)(x + (size_t)gn * 128 + cq);
        *(__half2*)&As[row * 136 + cq]     = __floats2half2_rn(v.x, v.y);
        *(__half2*)&As[row * 136 + cq + 2] = __floats2half2_rn(v.z, v.w);
    }

    unsigned asBase = (unsigned)__cvta_generic_to_shared(As);
    unsigned bsBase = (unsigned)__cvta_generic_to_shared(Bs);
    unsigned aAddr = asBase + (((m0 + r8 + (g8 & 1) * 8) * 136 + (g8 >> 1) * 8) << 1);
    unsigned bAddr0 = bsBase + (((r8 + (g8 >> 1) * 8) * 136 + (g8 & 1) * 8) << 1);

    for (int hb = 0; hb < 4; hb++) {
        __syncthreads();   // prior head's Cs reads complete before B fill
        if (tid < 64) {
            sA[tid] = as1[hb * 64 + tid];
            sD[tid] = ad1[hb * 64 + tid];
        }
#pragma unroll
        for (int i = 0; i < 8; i++) {
            int q = tid + i * 128;
            int nq = q >> 4, kq = (q & 15) * 8;
            *(uint4*)&Bs[nq * 136 + kq] =
                *(const uint4*)(g_W1h + (size_t)(hb * 64 + nq) * 128 + kq);
        }
        __syncthreads();

        float c[8][4];
#pragma unroll
        for (int j = 0; j < 8; j++)
#pragma unroll
            for (int q = 0; q < 4; q++) c[j][q] = 0.f;

#pragma unroll
        for (int ks = 0; ks < 8; ks++) {
            unsigned koff = (unsigned)(ks * 16 * 2);
            unsigned a0, a1, a2, a3;
            ldsm_x4(a0, a1, a2, a3, aAddr + koff);
#pragma unroll
            for (int p = 0; p < 4; p++) {
                unsigned b0, b1, b2, b3;
                ldsm_x4(b0, b1, b2, b3, bAddr0 + (unsigned)(p * 16 * 136 * 2) + koff);
                mma_f16(c[2*p][0],   c[2*p][1],   c[2*p][2],   c[2*p][3],
                        a0, a1, a2, a3, b0, b1);
                mma_f16(c[2*p+1][0], c[2*p+1][1], c[2*p+1][2], c[2*p+1][3],
                        a0, a1, a2, a3, b2, b3);
            }
        }

        // logits from registers: quad-reduce over c4
        {
            float s0 = 0.f, d0 = 0.f, s1 = 0.f, d1 = 0.f;
#pragma unroll
            for (int j = 0; j < 8; j++) {
                int col = j * 8 + 2 * c4;
                float2 av = *(const float2*)&sA[col];
                float2 dv = *(const float2*)&sD[col];
                s0 += c[j][0] * av.x + c[j][1] * av.y;
                d0 += c[j][0] * dv.x + c[j][1] * dv.y;
                s1 += c[j][2] * av.x + c[j][3] * av.y;
                d1 += c[j][2] * dv.x + c[j][3] * dv.y;
            }
#pragma unroll
            for (int o = 1; o < 4; o <<= 1) {
                s0 += __shfl_xor_sync(0xffffffffu, s0, o);
                d0 += __shfl_xor_sync(0xffffffffu, d0, o);
                s1 += __shfl_xor_sync(0xffffffffu, s1, o);
                d1 += __shfl_xor_sync(0xffffffffu, d1, o);
            }
            if (c4 == 0) {
                int gn0 = n0 + m0 + r4, gn1 = gn0 + 8;
                if (gn0 < NN) { g_ls1[gn0 * 4 + hb] = s0; g_ld1[gn0 * 4 + hb] = d0; }
                if (gn1 < NN) { g_ls1[gn1 * 4 + hb] = s1; g_ld1[gn1 * 4 + hb] = d1; }
            }
        }

        __syncthreads();   // all warps done reading Bs before Cs overwrite
#pragma unroll
        for (int j = 0; j < 8; j++) {
            int col = j * 8 + 2 * c4;
            *(__half2*)&Cs[(m0 + r4) * 72 + col]     = __floats2half2_rn(c[j][0], c[j][1]);
            *(__half2*)&Cs[(m0 + r4 + 8) * 72 + col] = __floats2half2_rn(c[j][2], c[j][3]);
        }
        __syncthreads();
#pragma unroll
        for (int i = 0; i < 4; i++) {
            int q = tid + i * 128;
            int row = q >> 3, cq = (q & 7) * 8;
            int gn = n0 + row;
            if (gn < NN)
                *(uint4*)(g_xl1h + (size_t)gn * 256 + hb * 64 + cq) =
                    *(uint4*)&Cs[row * 72 + cq];
        }
    }
}

// ------- aggregation layer1 (CSR; warp/dst; fp16 gather; unroll 4) ----------
__global__ __launch_bounds__(256) void k_agg1(const float* __restrict__ b1) {
    int wid = threadIdx.x >> 5, lane = threadIdx.x & 31;
    int dst = blockIdx.x * 8 + wid;
    if (dst >= NN) return;
    int2 od = g_offdeg[dst];
    int beg = od.x, end = od.x + od.y;
    int hh = lane >> 3;
    float ldv = g_ld1[dst * 4 + hh];
    float2 a0 = make_float2(0,0), a1 = make_float2(0,0);
    float2 a2 = make_float2(0,0), a3 = make_float2(0,0);
    float den = 0.f;
    int j = beg;
    for (; j + 4 <= end; j += 4) {
        int s[4];
#pragma unroll
        for (int u = 0; u < 4; u++) s[u] = __ldg(&g_src[j + u]);
        float wv[4];
#pragma unroll
        for (int u = 0; u < 4; u++) wv[u] = __expf(lrelu(__ldg(&g_ls1[s[u] * 4 + hh]) + ldv));
        uint4 hv[4];
#pragma unroll
        for (int u = 0; u < 4; u++) hv[u] = __ldg((const uint4*)(g_xl1h + (size_t)s[u] * 256 + lane * 8));
#pragma unroll
        for (int u = 0; u < 4; u++) {
            float wu = wv[u];
            den += wu;
            float2 v;
            v = __half22float2(*(__half2*)&hv[u].x); a0.x += wu * v.x; a0.y += wu * v.y;
            v = __half22float2(*(__half2*)&hv[u].y); a1.x += wu * v.x; a1.y += wu * v.y;
            v = __half22float2(*(__half2*)&hv[u].z); a2.x += wu * v.x; a2.y += wu * v.y;
            v = __half22float2(*(__half2*)&hv[u].w); a3.x += wu * v.x; a3.y += wu * v.y;
        }
    }
    for (; j < end; j++) {
        int s0 = __ldg(&g_src[j]);
        float w0 = __expf(lrelu(__ldg(&g_ls1[s0 * 4 + hh]) + ldv));
        uint4 hv0 = __ldg((const uint4*)(g_xl1h + (size_t)s0 * 256 + lane * 8));
        den += w0;
        float2 v;
        v = __half22float2(*(__half2*)&hv0.x); a0.x += w0 * v.x; a0.y += w0 * v.y;
        v = __half22float2(*(__half2*)&hv0.y); a1.x += w0 * v.x; a1.y += w0 * v.y;
        v = __half22float2(*(__half2*)&hv0.z); a2.x += w0 * v.x; a2.y += w0 * v.y;
        v = __half22float2(*(__half2*)&hv0.w); a3.x += w0 * v.x; a3.y += w0 * v.y;
    }
    float inv = 1.f / den;
    float4 bb0 = *(const float4*)(b1 + lane * 8);
    float4 bb1 = *(const float4*)(b1 + lane * 8 + 4);
    float o0 = fmaxf(a0.x * inv + bb0.x, 0.f);
    float o1 = fmaxf(a0.y * inv + bb0.y, 0.f);
    float o2 = fmaxf(a1.x * inv + bb0.z, 0.f);
    float o3 = fmaxf(a1.y * inv + bb0.w, 0.f);
    float o4 = fmaxf(a2.x * inv + bb1.x, 0.f);
    float o5 = fmaxf(a2.y * inv + bb1.y, 0.f);
    float o6 = fmaxf(a3.x * inv + bb1.z, 0.f);
    float o7 = fmaxf(a3.y * inv + bb1.w, 0.f);
    uint4 st;
    *(__half2*)&st.x = __floats2half2_rn(o0, o1);
    *(__half2*)&st.y = __floats2half2_rn(o2, o3);
    *(__half2*)&st.z = __floats2half2_rn(o4, o5);
    *(__half2*)&st.w = __floats2half2_rn(o6, o7);
    *(uint4*)(g_h1h + (size_t)dst * 256 + lane * 8) = st;
}

// ---------------- GEMM2 (fp16 mma) + fused logits2 --------------------------
// B tile = uint4 copies from pre-transposed g_W2h (pad 264: CF fragments).
__global__ __launch_bounds__(128) void k_gemm2(const float* __restrict__ as2,
                                               const float* __restrict__ ad2) {
    __shared__ __half As[64 * 136];   // [row][k-chunk 128], pad 136
    __shared__ __half Bs[32 * 264];   // [n][k 256], pad 264
    __shared__ __half Cs[64 * 40];    // [row][n 32], pad 40
    __shared__ float  sa[32], sd[32];
    int tid = threadIdx.x;
    int lane = tid & 31, w = tid >> 5;
    int n0 = blockIdx.x * 64;
    if (tid < 32) { sa[tid] = as2[tid]; sd[tid] = ad2[tid]; }
    // W2^T fp16 -> Bs via uint4 copy: 1024 uint4
#pragma unroll
    for (int i = 0; i < 8; i++) {
        int q = tid + i * 128;
        int n = q >> 5, kq = (q & 31) * 8;
        *(uint4*)&Bs[n * 264 + kq] = *(const uint4*)(g_W2h + (size_t)n * 256 + kq);
    }
    float c[4][4];
#pragma unroll
    for (int j = 0; j < 4; j++)
#pragma unroll
        for (int q = 0; q < 4; q++) c[j][q] = 0.f;
    int r4 = lane >> 2, c4 = lane & 3, m0 = w * 16;

    for (int ch = 0; ch < 2; ch++) {
        __syncthreads();
#pragma unroll
        for (int i = 0; i < 8; i++) {
            int q = tid + i * 128;
            int row = q >> 4, cq = (q & 15) * 8;
            int gn = n0 + row;
            uint4 v = make_uint4(0,0,0,0);
            if (gn < NN) v = *(const uint4*)(g_h1h + (size_t)gn * 256 + ch * 128 + cq);
            *(uint4*)&As[row * 136 + cq] = v;
        }
        __syncthreads();
#pragma unroll
        for (int ks = 0; ks < 8; ks++) {
            int kb = ks * 16;
            unsigned a0 = *(unsigned*)&As[(m0 + r4) * 136 + kb + 2 * c4];
            unsigned a1 = *(unsigned*)&As[(m0 + r4 + 8) * 136 + kb + 2 * c4];
            unsigned a2 = *(unsigned*)&As[(m0 + r4) * 136 + kb + 2 * c4 + 8];
            unsigned a3 = *(unsigned*)&As[(m0 + r4 + 8) * 136 + kb + 2 * c4 + 8];
            int kg = ch * 128 + kb + 2 * c4;
#pragma unroll
            for (int j = 0; j < 4; j++) {
                int n = j * 8 + r4;
                unsigned b0 = *(unsigned*)&Bs[n * 264 + kg];
                unsigned b1 = *(unsigned*)&Bs[n * 264 + kg + 8];
                mma_f16(c[j][0], c[j][1], c[j][2], c[j][3], a0, a1, a2, a3, b0, b1);
            }
        }
    }
    __syncthreads();
#pragma unroll
    for (int j = 0; j < 4; j++) {
        int col = j * 8 + 2 * c4;
        *(__half2*)&Cs[(m0 + r4) * 40 + col]     = __floats2half2_rn(c[j][0], c[j][1]);
        *(__half2*)&Cs[(m0 + r4 + 8) * 40 + col] = __floats2half2_rn(c[j][2], c[j][3]);
    }
    __syncthreads();
#pragma unroll
    for (int i = 0; i < 2; i++) {
        int q = tid + i * 128;
        int row = q >> 2, cq = (q & 3) * 8;
        int gn = n0 + row;
        if (gn < NN)
            *(uint4*)(g_xl2h + (size_t)gn * 32 + cq) = *(uint4*)&Cs[row * 40 + cq];
    }
    if (tid < 64) {
        int gn = n0 + tid;
        if (gn < NN) {
            float s = 0.f, d = 0.f;
#pragma unroll
            for (int cc = 0; cc < 32; cc++) {
                float v = __half2float(Cs[tid * 40 + cc]);
                s += v * sa[cc];
                d += v * sd[cc];
            }
            g_ls2[gn] = s;
            g_ld2[gn] = d;
        }
    }
}

// -------- fused tail: agg2 (into smem) + final GEMM (fp16 mma) --------------
// 256 threads, 64 nodes/block. Phase1: warp w aggregates dsts w*8..w*8+7
// (2 at a time, 16 lanes x 2ch) writing relu(.+b2) fp16 into As[row][k].
// Phase2: 8 warps, each 16 rows x 64 cols of out = h2 @ fcW^T + fcb.
__global__ __launch_bounds__(256) void k_tail(const float* __restrict__ b2,
                                              const float* __restrict__ fcb,
                                              float* __restrict__ out) {
    __shared__ __half As[64 * 40];    // [row][k 32], pad 40
    __shared__ __half Bs[128 * 40];   // [n][k 32], pad 40
    __shared__ float  sb[128];
    int tid = threadIdx.x;
    int lane = tid & 31, w = tid >> 5;
    int n0 = blockIdx.x * 64;
    if (tid < 128) sb[tid] = fcb[tid];
    // fcW^T fp16 -> Bs via uint4 copy: 512 uint4
#pragma unroll
    for (int i = 0; i < 2; i++) {
        int q = tid + i * 256;
        int n = q >> 2, kq = (q & 3) * 8;
        *(uint4*)&Bs[n * 40 + kq] = *(const uint4*)(g_fcWh + (size_t)n * 32 + kq);
    }

    // phase 1: aggregation
    int half = lane >> 4, hl = lane & 15, ch = hl * 2;
    float bx = b2[ch], by = b2[ch + 1];
#pragma unroll
    for (int it = 0; it < 4; it++) {
        int dl = w * 8 + it * 2 + half;
        int dst = n0 + dl;
        float2 acc = make_float2(0.f, 0.f);
        float den = 1.f;   // overwritten below; placeholder for dst>=NN path
        if (dst < NN) {
            int2 od = g_offdeg[dst];
            int beg = od.x, end = od.x + od.y;
            float ld2d = g_ld2[dst];
            den = 0.f;
            int j = beg;
            for (; j + 2 <= end; j += 2) {
                int s0 = __ldg(&g_src[j]);
                int s1 = __ldg(&g_src[j + 1]);
                float w0 = __expf(lrelu(__ldg(&g_ls2[s0]) + ld2d));
                float w1 = __expf(lrelu(__ldg(&g_ls2[s1]) + ld2d));
                float2 v0 = __half22float2(__ldg((const __half2*)(g_xl2h + (size_t)s0 * 32 + ch)));
                float2 v1 = __half22float2(__ldg((const __half2*)(g_xl2h + (size_t)s1 * 32 + ch)));
                den += w0 + w1;
                acc.x += w0 * v0.x + w1 * v1.x;
                acc.y += w0 * v0.y + w1 * v1.y;
            }
            if (j < end) {
                int s0 = __ldg(&g_src[j]);
                float w0 = __expf(lrelu(__ldg(&g_ls2[s0]) + ld2d));
                float2 v0 = __half22float2(__ldg((const __half2*)(g_xl2h + (size_t)s0 * 32 + ch)));
                den += w0;
                acc.x += w0 * v0.x;
                acc.y += w0 * v0.y;
            }
            float inv = 1.f / den;
            float hx = fmaxf(acc.x * inv + bx, 0.f);
            float hy = fmaxf(acc.y * inv + by, 0.f);
            *(__half2*)&As[dl * 40 + ch] = __floats2half2_rn(hx, hy);
        } else {
            *(__half2*)&As[dl * 40 + ch] = __floats2half2_rn(0.f, 0.f);
        }
    }
    __syncthreads();

    // phase 2: final GEMM; warp w -> rows m0..m0+15, cols nb..nb+63
    int r4 = lane >> 2, c4 = lane & 3;
    int m0 = (w >> 1) * 16, nb = (w & 1) * 64;
    float c[8][4];
#pragma unroll
    for (int j = 0; j < 8; j++)
#pragma unroll
        for (int q = 0; q < 4; q++) c[j][q] = 0.f;
#pragma unroll
    for (int ks = 0; ks < 2; ks++) {
        int kb = ks * 16;
        unsigned a0 = *(unsigned*)&As[(m0 + r4) * 40 + kb + 2 * c4];
        unsigned a1 = *(unsigned*)&As[(m0 + r4 + 8) * 40 + kb + 2 * c4];
        unsigned a2 = *(unsigned*)&As[(m0 + r4) * 40 + kb + 2 * c4 + 8];
        unsigned a3 = *(unsigned*)&As[(m0 + r4 + 8) * 40 + kb + 2 * c4 + 8];
#pragma unroll
        for (int j = 0; j < 8; j++) {
            int n = nb + j * 8 + r4;
            unsigned b0 = *(unsigned*)&Bs[n * 40 + kb + 2 * c4];
            unsigned b1 = *(unsigned*)&Bs[n * 40 + kb + 2 * c4 + 8];
            mma_f16(c[j][0], c[j][1], c[j][2], c[j][3], a0, a1, a2, a3, b0, b1);
        }
    }
    int row0 = n0 + m0 + r4, row1 = row0 + 8;
#pragma unroll
    for (int j = 0; j < 8; j++) {
        int col = nb + j * 8 + 2 * c4;
        float fx = sb[col], fy = sb[col + 1];
        if (row0 < NN) {
            float2 v0 = make_float2(c[j][0] + fx, c[j][1] + fy);
            *(float2*)(out + (size_t)row0 * 128 + col) = v0;
        }
        if (row1 < NN) {
            float2 v1 = make_float2(c[j][2] + fx, c[j][3] + fy);
            *(float2*)(out + (size_t)row1 * 128 + col) = v1;
        }
    }
}

// ---------------- launch ----------------
extern "C" void kernel_launch(void* const* d_in, const int* in_sizes, int n_in,
                              void* d_out, int out_size) {
    const float* x   = (const float*)d_in[0];
    const int*   ei  = (const int*)d_in[1];
    const float* W1  = (const float*)d_in[2];
    const float* as1 = (const float*)d_in[3];
    const float* ad1 = (const float*)d_in[4];
    const float* b1  = (const float*)d_in[5];
    const float* W2  = (const float*)d_in[6];
    const float* as2 = (const float*)d_in[7];
    const float* ad2 = (const float*)d_in[8];
    const float* b2  = (const float*)d_in[9];
    const float* fcW = (const float*)d_in[10];
    const float* fcb = (const float*)d_in[11];
    float* out = (float*)d_out;

    int g1 = (NN + 63) / 64;

    if (g_ss.ok) {
        cudaEventRecord(g_ss.fork, 0);
        cudaStreamWaitEvent(g_ss.s, g_ss.fork, 0);
        k_hist<<<(EE / 4 + 255) / 256, 256, 0, g_ss.s>>>(ei);
        k_scan<<<NB, 256, 0, g_ss.s>>>();
        k_scatter<<<(ET / 4 + 255) / 256, 256, 0, g_ss.s>>>(ei);
        cudaEventRecord(g_ss.join, g_ss.s);

        k_prep<<<128, 256>>>(W1, W2, fcW);
        k_gemm1<<<g1, 128>>>(x, as1, ad1);
        cudaStreamWaitEvent(0, g_ss.join, 0);
    } else {
        k_hist<<<(EE / 4 + 255) / 256, 256>>>(ei);
        k_scan<<<NB, 256>>>();
        k_scatter<<<(ET / 4 + 255) / 256, 256>>>(ei);
        k_prep<<<128, 256>>>(W1, W2, fcW);
        k_gemm1<<<g1, 128>>>(x, as1, ad1);
    }

    k_agg1<<<(NN + 7) / 8, 256>>>(b1);
    k_gemm2<<<(NN + 63) / 64, 128>>>(as2, ad2);
    k_tail<<<(NN + 63) / 64, 256>>>(b2, fcb, out);
}

// round 15
// speedup vs baseline: 1.0422x; 1.0422x over previous
#include <cuda_runtime.h>
#include <cuda_fp16.h>

// Problem constants
#define NN 50000
#define DD 128
#define EE 800000
#define ET (EE + NN)     // edges + self loops
#define F1 256
#define F2 32
#define NB ((NN + 255) / 256)   // 196 scan blocks

// ---------------- scratch (device globals; no allocations) ----------------
__device__ __half g_W1h[F1 * DD];    // W1^T [n=256][k=128] fp16
__device__ __half g_W2h[F2 * F1];    // W2^T [n=32][k=256] fp16
__device__ __half g_fcWh[DD * F2];   // fcW^T [n=128][k=32] fp16
__device__ __half g_xl1h[NN * F1];   // fp16 xl1 for aggregation gather
__device__ __half g_h1h[NN * F1];    // relu(agg1 + b1), fp16 for gemm2
__device__ float  g_ls1[NN * 4];
__device__ float  g_ld1[NN * 4];

__device__ __half g_xl2h[NN * F2];   // fp16 xl2 for agg2 gather
__device__ __half g_h2h[NN * F2];    // relu(agg2 + b2) fp16 (feeds final mma)
__device__ float  g_ls2[NN];
__device__ float  g_ld2[NN];

// CSR structures (g_cnt self-restores to 0; g_total reset in k_hist)
__device__ int  g_cnt[NN];
__device__ int2 g_offdeg[NN];        // (offset, degree) per dst
__device__ int  g_cur[NN];
__device__ int  g_total;
__device__ int  g_src[ET];           // src node per grouped edge

// ---------------- side stream for DAG capture (created once at load) -------
struct SideStream {
    cudaStream_t s = nullptr;
    cudaEvent_t fork = nullptr, join = nullptr;
    bool ok = false;
    SideStream() {
        if (cudaStreamCreateWithFlags(&s, cudaStreamNonBlocking) == cudaSuccess &&
            cudaEventCreateWithFlags(&fork, cudaEventDisableTiming) == cudaSuccess &&
            cudaEventCreateWithFlags(&join, cudaEventDisableTiming) == cudaSuccess)
            ok = true;
    }
};
static SideStream g_ss;

// ---------------- helpers ----------------
__device__ __forceinline__ float lrelu(float e) { return fmaxf(e, 0.2f * e); }

__device__ __forceinline__ void mma_f16(float& c0, float& c1, float& c2, float& c3,
                                        unsigned a0, unsigned a1, unsigned a2, unsigned a3,
                                        unsigned b0, unsigned b1) {
    asm volatile("mma.sync.aligned.m16n8k16.row.col.f32.f16.f16.f32 "
                 "{%0,%1,%2,%3}, {%4,%5,%6,%7}, {%8,%9}, {%0,%1,%2,%3};"
                 : "+f"(c0), "+f"(c1), "+f"(c2), "+f"(c3)
                 : "r"(a0), "r"(a1), "r"(a2), "r"(a3), "r"(b0), "r"(b1));
}
__device__ __forceinline__ void ldsm_x4(unsigned& r0, unsigned& r1, unsigned& r2, unsigned& r3,
                                        unsigned addr) {
    asm volatile("ldmatrix.sync.aligned.m8n8.x4.shared.b16 {%0,%1,%2,%3}, [%4];"
                 : "=r"(r0), "=r"(r1), "=r"(r2), "=r"(r3) : "r"(addr));
}

// ------------- weight prep: W1/W2/fcW -> fp16 transposed --------------------
__global__ void k_prep(const float* __restrict__ W1, const float* __restrict__ W2,
                       const float* __restrict__ fcW) {
    int i = blockIdx.x * 256 + threadIdx.x;   // 32768 threads
    {   // W1 [128][256] -> [n][k]
        int k = i >> 8, n = i & 255;
        g_W1h[n * 128 + k] = __float2half_rn(W1[i]);
    }
    if (i < 8192) {   // W2 [256][32] -> [n][k]
        int k = i >> 5, n = i & 31;
        g_W2h[n * 256 + k] = __float2half_rn(W2[i]);
    }
    if (i < 4096) {   // fcW [32][128] -> [n][k]
        int k = i >> 7, n = i & 127;
        g_fcWh[n * 32 + k] = __float2half_rn(fcW[i]);
    }
}

// ---------------- CSR build ----------------
__global__ void k_hist(const int* __restrict__ ei) {
    int i = blockIdx.x * blockDim.x + threadIdx.x;
    if (i == 0) g_total = 0;              // reset scan base counter
    if (i * 4 >= EE) return;
    int4 d4 = *(const int4*)(ei + EE + i * 4);
    atomicAdd(&g_cnt[d4.x], 1);
    atomicAdd(&g_cnt[d4.y], 1);
    atomicAdd(&g_cnt[d4.z], 1);
    atomicAdd(&g_cnt[d4.w], 1);
}

__global__ void k_scan() {
    __shared__ int wsum[8];
    __shared__ int sbase;
    int tid = threadIdx.x;
    int t = blockIdx.x * 256 + tid;
    int v = 0;
    if (t < NN) { v = g_cnt[t] + 1; g_cnt[t] = 0; }   // +1 = self loop; restore 0
    int lane = tid & 31, wid = tid >> 5;
    int incl = v;
#pragma unroll
    for (int o = 1; o < 32; o <<= 1) {
        int n = __shfl_up_sync(0xffffffffu, incl, o);
        if (lane >= o) incl += n;
    }
    if (lane == 31) wsum[wid] = incl;
    __syncthreads();
    if (wid == 0) {
        int s = (lane < 8) ? wsum[lane] : 0;
#pragma unroll
        for (int o = 1; o < 8; o <<= 1) {
            int n = __shfl_up_sync(0xffffffffu, s, o);
            if (lane >= o) s += n;
        }
        if (lane < 8) wsum[lane] = s;
        if (lane == 7) sbase = atomicAdd(&g_total, s);  // s = block total
    }
    __syncthreads();
    int base = (wid > 0) ? wsum[wid - 1] : 0;
    if (t < NN) {
        int off = sbase + base + incl - v;
        g_offdeg[t] = make_int2(off, v);
        g_cur[t] = off;
    }
}

__global__ void k_scatter(const int* __restrict__ ei) {
    int i = (blockIdx.x * blockDim.x + threadIdx.x) * 4;
    if (i >= ET) return;
    if (i < EE) {   // EE divisible by 4
        int4 s4 = *(const int4*)(ei + i);
        int4 d4 = *(const int4*)(ei + EE + i);
        int p0 = atomicAdd(&g_cur[d4.x], 1);
        int p1 = atomicAdd(&g_cur[d4.y], 1);
        int p2 = atomicAdd(&g_cur[d4.z], 1);
        int p3 = atomicAdd(&g_cur[d4.w], 1);
        g_src[p0] = s4.x;
        g_src[p1] = s4.y;
        g_src[p2] = s4.z;
        g_src[p3] = s4.w;
    } else {
#pragma unroll
        for (int u = 0; u < 4; u++) {
            int n = i + u - EE;
            int pos = atomicAdd(&g_cur[n], 1);
            g_src[pos] = n;
        }
    }
}

// ---------------- GEMM1 (fp16 mma + ldmatrix) + fused logits1 ---------------
__global__ __launch_bounds__(128) void k_gemm1(const float* __restrict__ x,
                                               const float* __restrict__ as1,
                                               const float* __restrict__ ad1) {
    __shared__ __half As[64 * 136];   // [m][k=128], pad 136
    __shared__ __half Bs[64 * 136];   // [n][k=128], pad 136
    __shared__ __half Cs[64 * 72];    // [m][n] fp16 staging
    __shared__ float  sA[64], sD[64];

    int tid = threadIdx.x;
    int lane = tid & 31, w = tid >> 5;
    int n0 = blockIdx.x * 64;
    int m0 = w * 16;
    int r4 = lane >> 2, c4 = lane & 3;
    int g8 = lane >> 3, r8 = lane & 7;

    // load x tile -> As fp16 ONCE
#pragma unroll
    for (int i = 0; i < 16; i++) {
        int q = tid + i * 128;
        int row = q >> 5, cq = (q & 31) * 4;
        int gn = n0 + row;
        float4 v = make_float4(0,0,0,0);
        if (gn < NN) v = *(const float4*)(x + (size_t)gn * 128 + cq);
        *(__half2*)&As[row * 136 + cq]     = __floats2half2_rn(v.x, v.y);
        *(__half2*)&As[row * 136 + cq + 2] = __floats2half2_rn(v.z, v.w);
    }

    unsigned asBase = (unsigned)__cvta_generic_to_shared(As);
    unsigned bsBase = (unsigned)__cvta_generic_to_shared(Bs);
    unsigned aAddr = asBase + (((m0 + r8 + (g8 & 1) * 8) * 136 + (g8 >> 1) * 8) << 1);
    unsigned bAddr0 = bsBase + (((r8 + (g8 >> 1) * 8) * 136 + (g8 & 1) * 8) << 1);

    for (int hb = 0; hb < 4; hb++) {
        __syncthreads();   // previous iteration's Bs/Cs/sA reads complete
        if (tid < 64) {
            sA[tid] = as1[hb * 64 + tid];
            sD[tid] = ad1[hb * 64 + tid];
        }
#pragma unroll
        for (int i = 0; i < 8; i++) {
            int q = tid + i * 128;
            int nq = q >> 4, kq = (q & 15) * 8;
            *(uint4*)&Bs[nq * 136 + kq] =
                *(const uint4*)(g_W1h + (size_t)(hb * 64 + nq) * 128 + kq);
        }
        __syncthreads();

        float c[8][4];
#pragma unroll
        for (int j = 0; j < 8; j++)
#pragma unroll
            for (int q = 0; q < 4; q++) c[j][q] = 0.f;

#pragma unroll
        for (int ks = 0; ks < 8; ks++) {
            unsigned koff = (unsigned)(ks * 16 * 2);
            unsigned a0, a1, a2, a3;
            ldsm_x4(a0, a1, a2, a3, aAddr + koff);
#pragma unroll
            for (int p = 0; p < 4; p++) {
                unsigned b0, b1, b2, b3;
                ldsm_x4(b0, b1, b2, b3, bAddr0 + (unsigned)(p * 16 * 136 * 2) + koff);
                mma_f16(c[2*p][0],   c[2*p][1],   c[2*p][2],   c[2*p][3],
                        a0, a1, a2, a3, b0, b1);
                mma_f16(c[2*p+1][0], c[2*p+1][1], c[2*p+1][2], c[2*p+1][3],
                        a0, a1, a2, a3, b2, b3);
            }
        }

        // logits from registers: quad-reduce over c4
        {
            float s0 = 0.f, d0 = 0.f, s1 = 0.f, d1 = 0.f;
#pragma unroll
            for (int j = 0; j < 8; j++) {
                int col = j * 8 + 2 * c4;
                float2 av = *(const float2*)&sA[col];
                float2 dv = *(const float2*)&sD[col];
                s0 += c[j][0] * av.x + c[j][1] * av.y;
                d0 += c[j][0] * dv.x + c[j][1] * dv.y;
                s1 += c[j][2] * av.x + c[j][3] * av.y;
                d1 += c[j][2] * dv.x + c[j][3] * dv.y;
            }
#pragma unroll
            for (int o = 1; o < 4; o <<= 1) {
                s0 += __shfl_xor_sync(0xffffffffu, s0, o);
                d0 += __shfl_xor_sync(0xffffffffu, d0, o);
                s1 += __shfl_xor_sync(0xffffffffu, s1, o);
                d1 += __shfl_xor_sync(0xffffffffu, d1, o);
            }
            if (c4 == 0) {
                int gn0 = n0 + m0 + r4, gn1 = gn0 + 8;
                if (gn0 < NN) { g_ls1[gn0 * 4 + hb] = s0; g_ld1[gn0 * 4 + hb] = d0; }
                if (gn1 < NN) { g_ls1[gn1 * 4 + hb] = s1; g_ld1[gn1 * 4 + hb] = d1; }
            }
        }

        // stage C as fp16, then coalesced store of the head slice
#pragma unroll
        for (int j = 0; j < 8; j++) {
            int col = j * 8 + 2 * c4;
            *(__half2*)&Cs[(m0 + r4) * 72 + col]     = __floats2half2_rn(c[j][0], c[j][1]);
            *(__half2*)&Cs[(m0 + r4 + 8) * 72 + col] = __floats2half2_rn(c[j][2], c[j][3]);
        }
        __syncthreads();
#pragma unroll
        for (int i = 0; i < 4; i++) {
            int q = tid + i * 128;
            int row = q >> 3, cq = (q & 7) * 8;
            int gn = n0 + row;
            if (gn < NN)
                *(uint4*)(g_xl1h + (size_t)gn * 256 + hb * 64 + cq) =
                    *(uint4*)&Cs[row * 72 + cq];
        }
    }
}

// ------- aggregation layer1 (CSR; warp/dst; fp16 gather; unroll 4) ----------
__global__ __launch_bounds__(256) void k_agg1(const float* __restrict__ b1) {
    int wid = threadIdx.x >> 5, lane = threadIdx.x & 31;
    int dst = blockIdx.x * 8 + wid;
    if (dst >= NN) return;
    int2 od = g_offdeg[dst];
    int beg = od.x, end = od.x + od.y;
    int hh = lane >> 3;
    float ldv = g_ld1[dst * 4 + hh];
    float2 a0 = make_float2(0,0), a1 = make_float2(0,0);
    float2 a2 = make_float2(0,0), a3 = make_float2(0,0);
    float den = 0.f;
    int j = beg;
    for (; j + 4 <= end; j += 4) {
        int s[4];
#pragma unroll
        for (int u = 0; u < 4; u++) s[u] = __ldg(&g_src[j + u]);
        float wv[4];
#pragma unroll
        for (int u = 0; u < 4; u++) wv[u] = __expf(lrelu(__ldg(&g_ls1[s[u] * 4 + hh]) + ldv));
        uint4 hv[4];
#pragma unroll
        for (int u = 0; u < 4; u++) hv[u] = __ldg((const uint4*)(g_xl1h + (size_t)s[u] * 256 + lane * 8));
#pragma unroll
        for (int u = 0; u < 4; u++) {
            float wu = wv[u];
            den += wu;
            float2 v;
            v = __half22float2(*(__half2*)&hv[u].x); a0.x += wu * v.x; a0.y += wu * v.y;
            v = __half22float2(*(__half2*)&hv[u].y); a1.x += wu * v.x; a1.y += wu * v.y;
            v = __half22float2(*(__half2*)&hv[u].z); a2.x += wu * v.x; a2.y += wu * v.y;
            v = __half22float2(*(__half2*)&hv[u].w); a3.x += wu * v.x; a3.y += wu * v.y;
        }
    }
    for (; j < end; j++) {
        int s0 = __ldg(&g_src[j]);
        float w0 = __expf(lrelu(__ldg(&g_ls1[s0 * 4 + hh]) + ldv));
        uint4 hv0 = __ldg((const uint4*)(g_xl1h + (size_t)s0 * 256 + lane * 8));
        den += w0;
        float2 v;
        v = __half22float2(*(__half2*)&hv0.x); a0.x += w0 * v.x; a0.y += w0 * v.y;
        v = __half22float2(*(__half2*)&hv0.y); a1.x += w0 * v.x; a1.y += w0 * v.y;
        v = __half22float2(*(__half2*)&hv0.z); a2.x += w0 * v.x; a2.y += w0 * v.y;
        v = __half22float2(*(__half2*)&hv0.w); a3.x += w0 * v.x; a3.y += w0 * v.y;
    }
    float inv = 1.f / den;
    float4 bb0 = *(const float4*)(b1 + lane * 8);
    float4 bb1 = *(const float4*)(b1 + lane * 8 + 4);
    float o0 = fmaxf(a0.x * inv + bb0.x, 0.f);
    float o1 = fmaxf(a0.y * inv + bb0.y, 0.f);
    float o2 = fmaxf(a1.x * inv + bb0.z, 0.f);
    float o3 = fmaxf(a1.y * inv + bb0.w, 0.f);
    float o4 = fmaxf(a2.x * inv + bb1.x, 0.f);
    float o5 = fmaxf(a2.y * inv + bb1.y, 0.f);
    float o6 = fmaxf(a3.x * inv + bb1.z, 0.f);
    float o7 = fmaxf(a3.y * inv + bb1.w, 0.f);
    uint4 st;
    *(__half2*)&st.x = __floats2half2_rn(o0, o1);
    *(__half2*)&st.y = __floats2half2_rn(o2, o3);
    *(__half2*)&st.z = __floats2half2_rn(o4, o5);
    *(__half2*)&st.w = __floats2half2_rn(o6, o7);
    *(uint4*)(g_h1h + (size_t)dst * 256 + lane * 8) = st;
}

// ---------------- GEMM2 (fp16 mma) + fused logits2 --------------------------
// B tile = uint4 copies from pre-transposed g_W2h (pad 264: CF fragments).
__global__ __launch_bounds__(128) void k_gemm2(const float* __restrict__ as2,
                                               const float* __restrict__ ad2) {
    __shared__ __half As[64 * 136];   // [row][k-chunk 128], pad 136
    __shared__ __half Bs[32 * 264];   // [n][k 256], pad 264
    __shared__ __half Cs[64 * 40];    // [row][n 32], pad 40
    __shared__ float  sa[32], sd[32];
    int tid = threadIdx.x;
    int lane = tid & 31, w = tid >> 5;
    int n0 = blockIdx.x * 64;
    if (tid < 32) { sa[tid] = as2[tid]; sd[tid] = ad2[tid]; }
    // W2^T fp16 -> Bs via uint4 copy: 1024 uint4
#pragma unroll
    for (int i = 0; i < 8; i++) {
        int q = tid + i * 128;
        int n = q >> 5, kq = (q & 31) * 8;
        *(uint4*)&Bs[n * 264 + kq] = *(const uint4*)(g_W2h + (size_t)n * 256 + kq);
    }
    float c[4][4];
#pragma unroll
    for (int j = 0; j < 4; j++)
#pragma unroll
        for (int q = 0; q < 4; q++) c[j][q] = 0.f;
    int r4 = lane >> 2, c4 = lane & 3, m0 = w * 16;

    for (int ch = 0; ch < 2; ch++) {
        __syncthreads();
#pragma unroll
        for (int i = 0; i < 8; i++) {
            int q = tid + i * 128;
            int row = q >> 4, cq = (q & 15) * 8;
            int gn = n0 + row;
            uint4 v = make_uint4(0,0,0,0);
            if (gn < NN) v = *(const uint4*)(g_h1h + (size_t)gn * 256 + ch * 128 + cq);
            *(uint4*)&As[row * 136 + cq] = v;
        }
        __syncthreads();
#pragma unroll
        for (int ks = 0; ks < 8; ks++) {
            int kb = ks * 16;
            unsigned a0 = *(unsigned*)&As[(m0 + r4) * 136 + kb + 2 * c4];
            unsigned a1 = *(unsigned*)&As[(m0 + r4 + 8) * 136 + kb + 2 * c4];
            unsigned a2 = *(unsigned*)&As[(m0 + r4) * 136 + kb + 2 * c4 + 8];
            unsigned a3 = *(unsigned*)&As[(m0 + r4 + 8) * 136 + kb + 2 * c4 + 8];
            int kg = ch * 128 + kb + 2 * c4;
#pragma unroll
            for (int j = 0; j < 4; j++) {
                int n = j * 8 + r4;
                unsigned b0 = *(unsigned*)&Bs[n * 264 + kg];
                unsigned b1 = *(unsigned*)&Bs[n * 264 + kg + 8];
                mma_f16(c[j][0], c[j][1], c[j][2], c[j][3], a0, a1, a2, a3, b0, b1);
            }
        }
    }
    __syncthreads();
#pragma unroll
    for (int j = 0; j < 4; j++) {
        int col = j * 8 + 2 * c4;
        *(__half2*)&Cs[(m0 + r4) * 40 + col]     = __floats2half2_rn(c[j][0], c[j][1]);
        *(__half2*)&Cs[(m0 + r4 + 8) * 40 + col] = __floats2half2_rn(c[j][2], c[j][3]);
    }
    __syncthreads();
#pragma unroll
    for (int i = 0; i < 2; i++) {
        int q = tid + i * 128;
        int row = q >> 2, cq = (q & 3) * 8;
        int gn = n0 + row;
        if (gn < NN)
            *(uint4*)(g_xl2h + (size_t)gn * 32 + cq) = *(uint4*)&Cs[row * 40 + cq];
    }
    if (tid < 64) {
        int gn = n0 + tid;
        if (gn < NN) {
            float s = 0.f, d = 0.f;
#pragma unroll
            for (int cc = 0; cc < 32; cc++) {
                float v = __half2float(Cs[tid * 40 + cc]);
                s += v * sa[cc];
                d += v * sd[cc];
            }
            g_ls2[gn] = s;
            g_ld2[gn] = d;
        }
    }
}

// ------- aggregation layer2 (CSR; 2 dst per warp; half2 channels) ----------
__global__ __launch_bounds__(256) void k_agg2(const float* __restrict__ b2) {
    int wid = threadIdx.x >> 5, lane = threadIdx.x & 31;
    int half = lane >> 4, hl = lane & 15;
    int dst = blockIdx.x * 16 + wid * 2 + half;
    if (dst >= NN) return;
    int2 od = g_offdeg[dst];
    int beg = od.x, end = od.x + od.y;
    float ld2d = g_ld2[dst];
    int ch = hl * 2;
    float2 acc = make_float2(0.f, 0.f);
    float den = 0.f;
    int j = beg;
    for (; j + 2 <= end; j += 2) {
        int s0 = __ldg(&g_src[j]);
        int s1 = __ldg(&g_src[j + 1]);
        float w0 = __expf(lrelu(__ldg(&g_ls2[s0]) + ld2d));
        float w1 = __expf(lrelu(__ldg(&g_ls2[s1]) + ld2d));
        float2 v0 = __half22float2(__ldg((const __half2*)(g_xl2h + (size_t)s0 * 32 + ch)));
        float2 v1 = __half22float2(__ldg((const __half2*)(g_xl2h + (size_t)s1 * 32 + ch)));
        den += w0 + w1;
        acc.x += w0 * v0.x + w1 * v1.x;
        acc.y += w0 * v0.y + w1 * v1.y;
    }
    if (j < end) {
        int s0 = __ldg(&g_src[j]);
        float w0 = __expf(lrelu(__ldg(&g_ls2[s0]) + ld2d));
        float2 v0 = __half22float2(__ldg((const __half2*)(g_xl2h + (size_t)s0 * 32 + ch)));
        den += w0;
        acc.x += w0 * v0.x;
        acc.y += w0 * v0.y;
    }
    float inv = 1.f / den;
    float hx = fmaxf(acc.x * inv + b2[ch], 0.f);
    float hy = fmaxf(acc.y * inv + b2[ch + 1], 0.f);
    *(__half2*)(g_h2h + (size_t)dst * 32 + ch) = __floats2half2_rn(hx, hy);
}

// ---------------- final (fp16 mma): out = h2 @ fc_W + fc_b ------------------
__global__ __launch_bounds__(128) void k_final(const float* __restrict__ fcb,
                                               float* __restrict__ out) {
    __shared__ __half As[64 * 40];    // [row][k 32], pad 40
    __shared__ __half Bs[128 * 40];   // [n][k 32], pad 40
    __shared__ float  sb[128];
    int tid = threadIdx.x;
    int lane = tid & 31, w = tid >> 5;
    int n0 = blockIdx.x * 64;
    sb[tid] = fcb[tid];
    // fcW^T fp16 -> Bs via uint4 copy: 512 uint4
#pragma unroll
    for (int i = 0; i < 4; i++) {
        int q = tid + i * 128;
        int n = q >> 2, kq = (q & 3) * 8;
        *(uint4*)&Bs[n * 40 + kq] = *(const uint4*)(g_fcWh + (size_t)n * 32 + kq);
    }
    // h2h tile -> As
#pragma unroll
    for (int i = 0; i < 2; i++) {
        int q = tid + i * 128;             // 256 uint4
        int row = q >> 2, cq = (q & 3) * 8;
        int gn = n0 + row;
        uint4 v = make_uint4(0,0,0,0);
        if (gn < NN) v = *(const uint4*)(g_h2h + (size_t)gn * 32 + cq);
        *(uint4*)&As[row * 40 + cq] = v;
    }
    __syncthreads();

    float c[16][4];
#pragma unroll
    for (int j = 0; j < 16; j++)
#pragma unroll
        for (int q = 0; q < 4; q++) c[j][q] = 0.f;
    int r4 = lane >> 2, c4 = lane & 3, m0 = w * 16;

#pragma unroll
    for (int ks = 0; ks < 2; ks++) {
        int kb = ks * 16;
        unsigned a0 = *(unsigned*)&As[(m0 + r4) * 40 + kb + 2 * c4];
        unsigned a1 = *(unsigned*)&As[(m0 + r4 + 8) * 40 + kb + 2 * c4];
        unsigned a2 = *(unsigned*)&As[(m0 + r4) * 40 + kb + 2 * c4 + 8];
        unsigned a3 = *(unsigned*)&As[(m0 + r4 + 8) * 40 + kb + 2 * c4 + 8];
#pragma unroll
        for (int j = 0; j < 16; j++) {
            int n = j * 8 + r4;
            unsigned b0 = *(unsigned*)&Bs[n * 40 + kb + 2 * c4];
            unsigned b1 = *(unsigned*)&Bs[n * 40 + kb + 2 * c4 + 8];
            mma_f16(c[j][0], c[j][1], c[j][2], c[j][3], a0, a1, a2, a3, b0, b1);
        }
    }
    int row0 = n0 + m0 + r4, row1 = row0 + 8;
#pragma unroll
    for (int j = 0; j < 16; j++) {
        int col = j * 8 + 2 * c4;
        float bx = sb[col], by = sb[col + 1];
        if (row0 < NN) {
            float2 v0 = make_float2(c[j][0] + bx, c[j][1] + by);
            *(float2*)(out + (size_t)row0 * 128 + col) = v0;
        }
        if (row1 < NN) {
            float2 v1 = make_float2(c[j][2] + bx, c[j][3] + by);
            *(float2*)(out + (size_t)row1 * 128 + col) = v1;
        }
    }
}

// ---------------- launch ----------------
extern "C" void kernel_launch(void* const* d_in, const int* in_sizes, int n_in,
                              void* d_out, int out_size) {
    const float* x   = (const float*)d_in[0];
    const int*   ei  = (const int*)d_in[1];
    const float* W1  = (const float*)d_in[2];
    const float* as1 = (const float*)d_in[3];
    const float* ad1 = (const float*)d_in[4];
    const float* b1  = (const float*)d_in[5];
    const float* W2  = (const float*)d_in[6];
    const float* as2 = (const float*)d_in[7];
    const float* ad2 = (const float*)d_in[8];
    const float* b2  = (const float*)d_in[9];
    const float* fcW = (const float*)d_in[10];
    const float* fcb = (const float*)d_in[11];
    float* out = (float*)d_out;

    int g1 = (NN + 63) / 64;

    if (g_ss.ok) {
        cudaEventRecord(g_ss.fork, 0);
        cudaStreamWaitEvent(g_ss.s, g_ss.fork, 0);
        k_hist<<<(EE / 4 + 255) / 256, 256, 0, g_ss.s>>>(ei);
        k_scan<<<NB, 256, 0, g_ss.s>>>();
        k_scatter<<<(ET / 4 + 255) / 256, 256, 0, g_ss.s>>>(ei);
        cudaEventRecord(g_ss.join, g_ss.s);

        k_prep<<<128, 256>>>(W1, W2, fcW);
        k_gemm1<<<g1, 128>>>(x, as1, ad1);
        cudaStreamWaitEvent(0, g_ss.join, 0);
    } else {
        k_hist<<<(EE / 4 + 255) / 256, 256>>>(ei);
        k_scan<<<NB, 256>>>();
        k_scatter<<<(ET / 4 + 255) / 256, 256>>>(ei);
        k_prep<<<128, 256>>>(W1, W2, fcW);
        k_gemm1<<<g1, 128>>>(x, as1, ad1);
    }

    k_agg1<<<(NN + 7) / 8, 256>>>(b1);
    k_gemm2<<<(NN + 63) / 64, 128>>>(as2, ad2);
    k_agg2<<<(NN + 15) / 16, 256>>>(b2);
    k_final<<<(NN + 63) / 64, 128>>>(fcb, out);
}

// round 16
// speedup vs baseline: 1.0731x; 1.0297x over previous
#include <cuda_runtime.h>
#include <cuda_fp16.h>

// Problem constants
#define NN 50000
#define DD 128
#define EE 800000
#define ET (EE + NN)     // edges + self loops
#define F1 256
#define F2 32
#define NB ((NN + 255) / 256)   // 196 scan blocks

// ---------------- scratch (device globals; no allocations) ----------------
__device__ __half g_W1h[F1 * DD];    // W1^T [n=256][k=128] fp16
__device__ __half g_W2h[F2 * F1];    // W2^T [n=32][k=256] fp16
__device__ __half g_fcWh[DD * F2];   // fcW^T [n=128][k=32] fp16
__device__ __half g_xl1h[NN * F1];   // fp16 xl1 for aggregation gather
__device__ __half g_h1h[NN * F1];    // relu(agg1 + b1), fp16 for gemm2
__device__ float  g_ls1[NN * 4];
__device__ float  g_ld1[NN * 4];

__device__ __half g_xl2h[NN * F2];   // fp16 xl2 for agg2 gather
__device__ __half g_h2h[NN * F2];    // relu(agg2 + b2) fp16 (feeds final mma)
__device__ float  g_ls2[NN];
__device__ float  g_ld2[NN];

// CSR structures (g_cnt self-restores to 0; g_total reset in k_hist)
__device__ int  g_cnt[NN];
__device__ int2 g_offdeg[NN];        // (offset, degree) per dst
__device__ int  g_cur[NN];
__device__ int  g_total;
__device__ int  g_src[ET];           // src node per grouped edge

// ---------------- side stream for DAG capture (created once at load) -------
struct SideStream {
    cudaStream_t s = nullptr;
    cudaEvent_t fork = nullptr, join = nullptr;
    bool ok = false;
    SideStream() {
        if (cudaStreamCreateWithFlags(&s, cudaStreamNonBlocking) == cudaSuccess &&
            cudaEventCreateWithFlags(&fork, cudaEventDisableTiming) == cudaSuccess &&
            cudaEventCreateWithFlags(&join, cudaEventDisableTiming) == cudaSuccess)
            ok = true;
    }
};
static SideStream g_ss;

// ---------------- helpers ----------------
__device__ __forceinline__ float lrelu(float e) { return fmaxf(e, 0.2f * e); }

__device__ __forceinline__ void mma_f16(float& c0, float& c1, float& c2, float& c3,
                                        unsigned a0, unsigned a1, unsigned a2, unsigned a3,
                                        unsigned b0, unsigned b1) {
    asm volatile("mma.sync.aligned.m16n8k16.row.col.f32.f16.f16.f32 "
                 "{%0,%1,%2,%3}, {%4,%5,%6,%7}, {%8,%9}, {%0,%1,%2,%3};"
                 : "+f"(c0), "+f"(c1), "+f"(c2), "+f"(c3)
                 : "r"(a0), "r"(a1), "r"(a2), "r"(a3), "r"(b0), "r"(b1));
}
__device__ __forceinline__ void ldsm_x4(unsigned& r0, unsigned& r1, unsigned& r2, unsigned& r3,
                                        unsigned addr) {
    asm volatile("ldmatrix.sync.aligned.m8n8.x4.shared.b16 {%0,%1,%2,%3}, [%4];"
                 : "=r"(r0), "=r"(r1), "=r"(r2), "=r"(r3) : "r"(addr));
}

// ------------- weight prep (split): W1 on main; W2/fcW on side --------------
__global__ void k_prep1(const float* __restrict__ W1) {
    int i = blockIdx.x * 256 + threadIdx.x;   // 32768 threads
    int k = i >> 8, n = i & 255;
    g_W1h[n * 128 + k] = __float2half_rn(W1[i]);
}
__global__ void k_prep2(const float* __restrict__ W2, const float* __restrict__ fcW) {
    int i = blockIdx.x * 256 + threadIdx.x;   // 8192 threads
    {   // W2 [256][32] -> [n][k]
        int k = i >> 5, n = i & 31;
        g_W2h[n * 256 + k] = __float2half_rn(W2[i]);
    }
    if (i < 4096) {   // fcW [32][128] -> [n][k]
        int k = i >> 7, n = i & 127;
        g_fcWh[n * 32 + k] = __float2half_rn(fcW[i]);
    }
}

// ---------------- CSR build ----------------
__global__ void k_hist(const int* __restrict__ ei) {
    int i = blockIdx.x * blockDim.x + threadIdx.x;
    if (i == 0) g_total = 0;              // reset scan base counter
    if (i * 4 >= EE) return;
    int4 d4 = *(const int4*)(ei + EE + i * 4);
    atomicAdd(&g_cnt[d4.x], 1);
    atomicAdd(&g_cnt[d4.y], 1);
    atomicAdd(&g_cnt[d4.z], 1);
    atomicAdd(&g_cnt[d4.w], 1);
}

__global__ void k_scan() {
    __shared__ int wsum[8];
    __shared__ int sbase;
    int tid = threadIdx.x;
    int t = blockIdx.x * 256 + tid;
    int v = 0;
    if (t < NN) { v = g_cnt[t] + 1; g_cnt[t] = 0; }   // +1 = self loop; restore 0
    int lane = tid & 31, wid = tid >> 5;
    int incl = v;
#pragma unroll
    for (int o = 1; o < 32; o <<= 1) {
        int n = __shfl_up_sync(0xffffffffu, incl, o);
        if (lane >= o) incl += n;
    }
    if (lane == 31) wsum[wid] = incl;
    __syncthreads();
    if (wid == 0) {
        int s = (lane < 8) ? wsum[lane] : 0;
#pragma unroll
        for (int o = 1; o < 8; o <<= 1) {
            int n = __shfl_up_sync(0xffffffffu, s, o);
            if (lane >= o) s += n;
        }
        if (lane < 8) wsum[lane] = s;
        if (lane == 7) sbase = atomicAdd(&g_total, s);  // s = block total
    }
    __syncthreads();
    int base = (wid > 0) ? wsum[wid - 1] : 0;
    if (t < NN) {
        int off = sbase + base + incl - v;
        g_offdeg[t] = make_int2(off, v);
        g_cur[t] = off;
    }
}

__global__ void k_scatter(const int* __restrict__ ei) {
    int i = (blockIdx.x * blockDim.x + threadIdx.x) * 4;
    if (i >= ET) return;
    if (i < EE) {   // EE divisible by 4
        int4 s4 = *(const int4*)(ei + i);
        int4 d4 = *(const int4*)(ei + EE + i);
        int p0 = atomicAdd(&g_cur[d4.x], 1);
        int p1 = atomicAdd(&g_cur[d4.y], 1);
        int p2 = atomicAdd(&g_cur[d4.z], 1);
        int p3 = atomicAdd(&g_cur[d4.w], 1);
        g_src[p0] = s4.x;
        g_src[p1] = s4.y;
        g_src[p2] = s4.z;
        g_src[p3] = s4.w;
    } else {
#pragma unroll
        for (int u = 0; u < 4; u++) {
            int n = i + u - EE;
            int pos = atomicAdd(&g_cur[n], 1);
            g_src[pos] = n;
        }
    }
}

// ---------------- GEMM1 (fp16 mma + ldmatrix) + fused logits1 ---------------
// Cs aliased onto Bs (Bs dead after mainloop; refilled next head) -> 35.2KB
// smem, 6 blocks/SM.
__global__ __launch_bounds__(128) void k_gemm1(const float* __restrict__ x,
                                               const float* __restrict__ as1,
                                               const float* __restrict__ ad1) {
    __shared__ __half As[64 * 136];   // [m][k=128], pad 136
    __shared__ __half Bs[64 * 136];   // [n][k=128]; reused as Cs[64][72]
    __shared__ float  sA[64], sD[64];
    __half* Cs = Bs;

    int tid = threadIdx.x;
    int lane = tid & 31, w = tid >> 5;
    int n0 = blockIdx.x * 64;
    int m0 = w * 16;
    int r4 = lane >> 2, c4 = lane & 3;
    int g8 = lane >> 3, r8 = lane & 7;

    // load x tile -> As fp16 ONCE
#pragma unroll
    for (int i = 0; i < 16; i++) {
        int q = tid + i * 128;
        int row = q >> 5, cq = (q & 31) * 4;
        int gn = n0 + row;
        float4 v = make_float4(0,0,0,0);
        if (gn < NN) v = *(const float4*)(x + (size_t)gn * 128 + cq);
        *(__half2*)&As[row * 136 + cq]     = __floats2half2_rn(v.x, v.y);
        *(__half2*)&As[row * 136 + cq + 2] = __floats2half2_rn(v.z, v.w);
    }

    unsigned asBase = (unsigned)__cvta_generic_to_shared(As);
    unsigned bsBase = (unsigned)__cvta_generic_to_shared(Bs);
    unsigned aAddr = asBase + (((m0 + r8 + (g8 & 1) * 8) * 136 + (g8 >> 1) * 8) << 1);
    unsigned bAddr0 = bsBase + (((r8 + (g8 >> 1) * 8) * 136 + (g8 & 1) * 8) << 1);

    for (int hb = 0; hb < 4; hb++) {
        __syncthreads();   // prior head's Cs reads complete before B fill
        if (tid < 64) {
            sA[tid] = as1[hb * 64 + tid];
            sD[tid] = ad1[hb * 64 + tid];
        }
#pragma unroll
        for (int i = 0; i < 8; i++) {
            int q = tid + i * 128;
            int nq = q >> 4, kq = (q & 15) * 8;
            *(uint4*)&Bs[nq * 136 + kq] =
                *(const uint4*)(g_W1h + (size_t)(hb * 64 + nq) * 128 + kq);
        }
        __syncthreads();

        float c[8][4];
#pragma unroll
        for (int j = 0; j < 8; j++)
#pragma unroll
            for (int q = 0; q < 4; q++) c[j][q] = 0.f;

#pragma unroll
        for (int ks = 0; ks < 8; ks++) {
            unsigned koff = (unsigned)(ks * 16 * 2);
            unsigned a0, a1, a2, a3;
            ldsm_x4(a0, a1, a2, a3, aAddr + koff);
#pragma unroll
            for (int p = 0; p < 4; p++) {
                unsigned b0, b1, b2, b3;
                ldsm_x4(b0, b1, b2, b3, bAddr0 + (unsigned)(p * 16 * 136 * 2) + koff);
                mma_f16(c[2*p][0],   c[2*p][1],   c[2*p][2],   c[2*p][3],
                        a0, a1, a2, a3, b0, b1);
                mma_f16(c[2*p+1][0], c[2*p+1][1], c[2*p+1][2], c[2*p+1][3],
                        a0, a1, a2, a3, b2, b3);
            }
        }

        // logits from registers: quad-reduce over c4
        {
            float s0 = 0.f, d0 = 0.f, s1 = 0.f, d1 = 0.f;
#pragma unroll
            for (int j = 0; j < 8; j++) {
                int col = j * 8 + 2 * c4;
                float2 av = *(const float2*)&sA[col];
                float2 dv = *(const float2*)&sD[col];
                s0 += c[j][0] * av.x + c[j][1] * av.y;
                d0 += c[j][0] * dv.x + c[j][1] * dv.y;
                s1 += c[j][2] * av.x + c[j][3] * av.y;
                d1 += c[j][2] * dv.x + c[j][3] * dv.y;
            }
#pragma unroll
            for (int o = 1; o < 4; o <<= 1) {
                s0 += __shfl_xor_sync(0xffffffffu, s0, o);
                d0 += __shfl_xor_sync(0xffffffffu, d0, o);
                s1 += __shfl_xor_sync(0xffffffffu, s1, o);
                d1 += __shfl_xor_sync(0xffffffffu, d1, o);
            }
            if (c4 == 0) {
                int gn0 = n0 + m0 + r4, gn1 = gn0 + 8;
                if (gn0 < NN) { g_ls1[gn0 * 4 + hb] = s0; g_ld1[gn0 * 4 + hb] = d0; }
                if (gn1 < NN) { g_ls1[gn1 * 4 + hb] = s1; g_ld1[gn1 * 4 + hb] = d1; }
            }
        }

        __syncthreads();   // all warps done reading Bs before Cs overwrite
#pragma unroll
        for (int j = 0; j < 8; j++) {
            int col = j * 8 + 2 * c4;
            *(__half2*)&Cs[(m0 + r4) * 72 + col]     = __floats2half2_rn(c[j][0], c[j][1]);
            *(__half2*)&Cs[(m0 + r4 + 8) * 72 + col] = __floats2half2_rn(c[j][2], c[j][3]);
        }
        __syncthreads();
#pragma unroll
        for (int i = 0; i < 4; i++) {
            int q = tid + i * 128;
            int row = q >> 3, cq = (q & 7) * 8;
            int gn = n0 + row;
            if (gn < NN)
                *(uint4*)(g_xl1h + (size_t)gn * 256 + hb * 64 + cq) =
                    *(uint4*)&Cs[row * 72 + cq];
        }
    }
}

// ------- aggregation layer1 (CSR; warp/dst; fp16 gather; unroll 4) ----------
__global__ __launch_bounds__(256) void k_agg1(const float* __restrict__ b1) {
    int wid = threadIdx.x >> 5, lane = threadIdx.x & 31;
    int dst = blockIdx.x * 8 + wid;
    if (dst >= NN) return;
    int2 od = g_offdeg[dst];
    int beg = od.x, end = od.x + od.y;
    int hh = lane >> 3;
    float ldv = g_ld1[dst * 4 + hh];
    float2 a0 = make_float2(0,0), a1 = make_float2(0,0);
    float2 a2 = make_float2(0,0), a3 = make_float2(0,0);
    float den = 0.f;
    int j = beg;
    for (; j + 4 <= end; j += 4) {
        int s[4];
#pragma unroll
        for (int u = 0; u < 4; u++) s[u] = __ldg(&g_src[j + u]);
        float wv[4];
#pragma unroll
        for (int u = 0; u < 4; u++) wv[u] = __expf(lrelu(__ldg(&g_ls1[s[u] * 4 + hh]) + ldv));
        uint4 hv[4];
#pragma unroll
        for (int u = 0; u < 4; u++) hv[u] = __ldg((const uint4*)(g_xl1h + (size_t)s[u] * 256 + lane * 8));
#pragma unroll
        for (int u = 0; u < 4; u++) {
            float wu = wv[u];
            den += wu;
            float2 v;
            v = __half22float2(*(__half2*)&hv[u].x); a0.x += wu * v.x; a0.y += wu * v.y;
            v = __half22float2(*(__half2*)&hv[u].y); a1.x += wu * v.x; a1.y += wu * v.y;
            v = __half22float2(*(__half2*)&hv[u].z); a2.x += wu * v.x; a2.y += wu * v.y;
            v = __half22float2(*(__half2*)&hv[u].w); a3.x += wu * v.x; a3.y += wu * v.y;
        }
    }
    for (; j < end; j++) {
        int s0 = __ldg(&g_src[j]);
        float w0 = __expf(lrelu(__ldg(&g_ls1[s0 * 4 + hh]) + ldv));
        uint4 hv0 = __ldg((const uint4*)(g_xl1h + (size_t)s0 * 256 + lane * 8));
        den += w0;
        float2 v;
        v = __half22float2(*(__half2*)&hv0.x); a0.x += w0 * v.x; a0.y += w0 * v.y;
        v = __half22float2(*(__half2*)&hv0.y); a1.x += w0 * v.x; a1.y += w0 * v.y;
        v = __half22float2(*(__half2*)&hv0.z); a2.x += w0 * v.x; a2.y += w0 * v.y;
        v = __half22float2(*(__half2*)&hv0.w); a3.x += w0 * v.x; a3.y += w0 * v.y;
    }
    float inv = 1.f / den;
    float4 bb0 = *(const float4*)(b1 + lane * 8);
    float4 bb1 = *(const float4*)(b1 + lane * 8 + 4);
    float o0 = fmaxf(a0.x * inv + bb0.x, 0.f);
    float o1 = fmaxf(a0.y * inv + bb0.y, 0.f);
    float o2 = fmaxf(a1.x * inv + bb0.z, 0.f);
    float o3 = fmaxf(a1.y * inv + bb0.w, 0.f);
    float o4 = fmaxf(a2.x * inv + bb1.x, 0.f);
    float o5 = fmaxf(a2.y * inv + bb1.y, 0.f);
    float o6 = fmaxf(a3.x * inv + bb1.z, 0.f);
    float o7 = fmaxf(a3.y * inv + bb1.w, 0.f);
    uint4 st;
    *(__half2*)&st.x = __floats2half2_rn(o0, o1);
    *(__half2*)&st.y = __floats2half2_rn(o2, o3);
    *(__half2*)&st.z = __floats2half2_rn(o4, o5);
    *(__half2*)&st.w = __floats2half2_rn(o6, o7);
    *(uint4*)(g_h1h + (size_t)dst * 256 + lane * 8) = st;
}

// ---------------- GEMM2 (fp16 mma) + fused logits2 --------------------------
__global__ __launch_bounds__(128) void k_gemm2(const float* __restrict__ as2,
                                               const float* __restrict__ ad2) {
    __shared__ __half As[64 * 136];   // [row][k-chunk 128], pad 136
    __shared__ __half Bs[32 * 264];   // [n][k 256], pad 264
    __shared__ __half Cs[64 * 40];    // [row][n 32], pad 40
    __shared__ float  sa[32], sd[32];
    int tid = threadIdx.x;
    int lane = tid & 31, w = tid >> 5;
    int n0 = blockIdx.x * 64;
    if (tid < 32) { sa[tid] = as2[tid]; sd[tid] = ad2[tid]; }
    // W2^T fp16 -> Bs via uint4 copy: 1024 uint4
#pragma unroll
    for (int i = 0; i < 8; i++) {
        int q = tid + i * 128;
        int n = q >> 5, kq = (q & 31) * 8;
        *(uint4*)&Bs[n * 264 + kq] = *(const uint4*)(g_W2h + (size_t)n * 256 + kq);
    }
    float c[4][4];
#pragma unroll
    for (int j = 0; j < 4; j++)
#pragma unroll
        for (int q = 0; q < 4; q++) c[j][q] = 0.f;
    int r4 = lane >> 2, c4 = lane & 3, m0 = w * 16;

    for (int ch = 0; ch < 2; ch++) {
        __syncthreads();
#pragma unroll
        for (int i = 0; i < 8; i++) {
            int q = tid + i * 128;
            int row = q >> 4, cq = (q & 15) * 8;
            int gn = n0 + row;
            uint4 v = make_uint4(0,0,0,0);
            if (gn < NN) v = *(const uint4*)(g_h1h + (size_t)gn * 256 + ch * 128 + cq);
            *(uint4*)&As[row * 136 + cq] = v;
        }
        __syncthreads();
#pragma unroll
        for (int ks = 0; ks < 8; ks++) {
            int kb = ks * 16;
            unsigned a0 = *(unsigned*)&As[(m0 + r4) * 136 + kb + 2 * c4];
            unsigned a1 = *(unsigned*)&As[(m0 + r4 + 8) * 136 + kb + 2 * c4];
            unsigned a2 = *(unsigned*)&As[(m0 + r4) * 136 + kb + 2 * c4 + 8];
            unsigned a3 = *(unsigned*)&As[(m0 + r4 + 8) * 136 + kb + 2 * c4 + 8];
            int kg = ch * 128 + kb + 2 * c4;
#pragma unroll
            for (int j = 0; j < 4; j++) {
                int n = j * 8 + r4;
                unsigned b0 = *(unsigned*)&Bs[n * 264 + kg];
                unsigned b1 = *(unsigned*)&Bs[n * 264 + kg + 8];
                mma_f16(c[j][0], c[j][1], c[j][2], c[j][3], a0, a1, a2, a3, b0, b1);
            }
        }
    }
    __syncthreads();
#pragma unroll
    for (int j = 0; j < 4; j++) {
        int col = j * 8 + 2 * c4;
        *(__half2*)&Cs[(m0 + r4) * 40 + col]     = __floats2half2_rn(c[j][0], c[j][1]);
        *(__half2*)&Cs[(m0 + r4 + 8) * 40 + col] = __floats2half2_rn(c[j][2], c[j][3]);
    }
    __syncthreads();
#pragma unroll
    for (int i = 0; i < 2; i++) {
        int q = tid + i * 128;
        int row = q >> 2, cq = (q & 3) * 8;
        int gn = n0 + row;
        if (gn < NN)
            *(uint4*)(g_xl2h + (size_t)gn * 32 + cq) = *(uint4*)&Cs[row * 40 + cq];
    }
    if (tid < 64) {
        int gn = n0 + tid;
        if (gn < NN) {
            float s = 0.f, d = 0.f;
#pragma unroll
            for (int cc = 0; cc < 32; cc++) {
                float v = __half2float(Cs[tid * 40 + cc]);
                s += v * sa[cc];
                d += v * sd[cc];
            }
            g_ls2[gn] = s;
            g_ld2[gn] = d;
        }
    }
}

// ------- aggregation layer2 (CSR; 2 dst per warp; half2 channels) ----------
__global__ __launch_bounds__(256) void k_agg2(const float* __restrict__ b2) {
    int wid = threadIdx.x >> 5, lane = threadIdx.x & 31;
    int half = lane >> 4, hl = lane & 15;
    int dst = blockIdx.x * 16 + wid * 2 + half;
    if (dst >= NN) return;
    int2 od = g_offdeg[dst];
    int beg = od.x, end = od.x + od.y;
    float ld2d = g_ld2[dst];
    int ch = hl * 2;
    float2 acc = make_float2(0.f, 0.f);
    float den = 0.f;
    int j = beg;
    for (; j + 2 <= end; j += 2) {
        int s0 = __ldg(&g_src[j]);
        int s1 = __ldg(&g_src[j + 1]);
        float w0 = __expf(lrelu(__ldg(&g_ls2[s0]) + ld2d));
        float w1 = __expf(lrelu(__ldg(&g_ls2[s1]) + ld2d));
        float2 v0 = __half22float2(__ldg((const __half2*)(g_xl2h + (size_t)s0 * 32 + ch)));
        float2 v1 = __half22float2(__ldg((const __half2*)(g_xl2h + (size_t)s1 * 32 + ch)));
        den += w0 + w1;
        acc.x += w0 * v0.x + w1 * v1.x;
        acc.y += w0 * v0.y + w1 * v1.y;
    }
    if (j < end) {
        int s0 = __ldg(&g_src[j]);
        float w0 = __expf(lrelu(__ldg(&g_ls2[s0]) + ld2d));
        float2 v0 = __half22float2(__ldg((const __half2*)(g_xl2h + (size_t)s0 * 32 + ch)));
        den += w0;
        acc.x += w0 * v0.x;
        acc.y += w0 * v0.y;
    }
    float inv = 1.f / den;
    float hx = fmaxf(acc.x * inv + b2[ch], 0.f);
    float hy = fmaxf(acc.y * inv + b2[ch + 1], 0.f);
    *(__half2*)(g_h2h + (size_t)dst * 32 + ch) = __floats2half2_rn(hx, hy);
}

// ---------------- final (fp16 mma): out = h2 @ fc_W + fc_b ------------------
__global__ __launch_bounds__(128) void k_final(const float* __restrict__ fcb,
                                               float* __restrict__ out) {
    __shared__ __half As[64 * 40];    // [row][k 32], pad 40
    __shared__ __half Bs[128 * 40];   // [n][k 32], pad 40
    __shared__ float  sb[128];
    int tid = threadIdx.x;
    int lane = tid & 31, w = tid >> 5;
    int n0 = blockIdx.x * 64;
    sb[tid] = fcb[tid];
    // fcW^T fp16 -> Bs via uint4 copy: 512 uint4
#pragma unroll
    for (int i = 0; i < 4; i++) {
        int q = tid + i * 128;
        int n = q >> 2, kq = (q & 3) * 8;
        *(uint4*)&Bs[n * 40 + kq] = *(const uint4*)(g_fcWh + (size_t)n * 32 + kq);
    }
    // h2h tile -> As
#pragma unroll
    for (int i = 0; i < 2; i++) {
        int q = tid + i * 128;             // 256 uint4
        int row = q >> 2, cq = (q & 3) * 8;
        int gn = n0 + row;
        uint4 v = make_uint4(0,0,0,0);
        if (gn < NN) v = *(const uint4*)(g_h2h + (size_t)gn * 32 + cq);
        *(uint4*)&As[row * 40 + cq] = v;
    }
    __syncthreads();

    float c[16][4];
#pragma unroll
    for (int j = 0; j < 16; j++)
#pragma unroll
        for (int q = 0; q < 4; q++) c[j][q] = 0.f;
    int r4 = lane >> 2, c4 = lane & 3, m0 = w * 16;

#pragma unroll
    for (int ks = 0; ks < 2; ks++) {
        int kb = ks * 16;
        unsigned a0 = *(unsigned*)&As[(m0 + r4) * 40 + kb + 2 * c4];
        unsigned a1 = *(unsigned*)&As[(m0 + r4 + 8) * 40 + kb + 2 * c4];
        unsigned a2 = *(unsigned*)&As[(m0 + r4) * 40 + kb + 2 * c4 + 8];
        unsigned a3 = *(unsigned*)&As[(m0 + r4 + 8) * 40 + kb + 2 * c4 + 8];
#pragma unroll
        for (int j = 0; j < 16; j++) {
            int n = j * 8 + r4;
            unsigned b0 = *(unsigned*)&Bs[n * 40 + kb + 2 * c4];
            unsigned b1 = *(unsigned*)&Bs[n * 40 + kb + 2 * c4 + 8];
            mma_f16(c[j][0], c[j][1], c[j][2], c[j][3], a0, a1, a2, a3, b0, b1);
        }
    }
    int row0 = n0 + m0 + r4, row1 = row0 + 8;
#pragma unroll
    for (int j = 0; j < 16; j++) {
        int col = j * 8 + 2 * c4;
        float bx = sb[col], by = sb[col + 1];
        if (row0 < NN) {
            float2 v0 = make_float2(c[j][0] + bx, c[j][1] + by);
            *(float2*)(out + (size_t)row0 * 128 + col) = v0;
        }
        if (row1 < NN) {
            float2 v1 = make_float2(c[j][2] + bx, c[j][3] + by);
            *(float2*)(out + (size_t)row1 * 128 + col) = v1;
        }
    }
}

// ---------------- launch ----------------
extern "C" void kernel_launch(void* const* d_in, const int* in_sizes, int n_in,
                              void* d_out, int out_size) {
    const float* x   = (const float*)d_in[0];
    const int*   ei  = (const int*)d_in[1];
    const float* W1  = (const float*)d_in[2];
    const float* as1 = (const float*)d_in[3];
    const float* ad1 = (const float*)d_in[4];
    const float* b1  = (const float*)d_in[5];
    const float* W2  = (const float*)d_in[6];
    const float* as2 = (const float*)d_in[7];
    const float* ad2 = (const float*)d_in[8];
    const float* b2  = (const float*)d_in[9];
    const float* fcW = (const float*)d_in[10];
    const float* fcb = (const float*)d_in[11];
    float* out = (float*)d_out;

    int g1 = (NN + 63) / 64;

    if (g_ss.ok) {
        cudaEventRecord(g_ss.fork, 0);
        cudaStreamWaitEvent(g_ss.s, g_ss.fork, 0);
        k_prep2<<<32, 256, 0, g_ss.s>>>(W2, fcW);
        k_hist<<<(EE / 4 + 255) / 256, 256, 0, g_ss.s>>>(ei);
        k_scan<<<NB, 256, 0, g_ss.s>>>();
        k_scatter<<<(ET / 4 + 255) / 256, 256, 0, g_ss.s>>>(ei);
        cudaEventRecord(g_ss.join, g_ss.s);

        k_prep1<<<128, 256>>>(W1);
        k_gemm1<<<g1, 128>>>(x, as1, ad1);
        cudaStreamWaitEvent(0, g_ss.join, 0);
    } else {
        k_prep2<<<32, 256>>>(W2, fcW);
        k_hist<<<(EE / 4 + 255) / 256, 256>>>(ei);
        k_scan<<<NB, 256>>>();
        k_scatter<<<(ET / 4 + 255) / 256, 256>>>(ei);
        k_prep1<<<128, 256>>>(W1);
        k_gemm1<<<g1, 128>>>(x, as1, ad1);
    }

    k_agg1<<<(NN + 7) / 8, 256>>>(b1);
    k_gemm2<<<(NN + 63) / 64, 128>>>(as2, ad2);
    k_agg2<<<(NN + 15) / 16, 256>>>(b2);
    k_final<<<(NN + 63) / 64, 128>>>(fcb, out);
}